// round 1
// baseline (speedup 1.0000x reference)
#include <cuda_runtime.h>
#include <math.h>

// ---------------------------------------------------------------------------
// GCN: h1 = relu(Anorm @ (x@W1) + b1); h2 = Anorm @ (h1@W2) + b2;
//      out = log_softmax(h2 @ Wl + bl)
// Anorm = sym-normalized adjacency with self loops (deg counted on dst).
// Strategy: build CSR (by dst) once per launch, pull-based aggregation
// (no float atomics), fp32 SIMT GEMMs, fused final GEMM + log_softmax.
// ---------------------------------------------------------------------------

#define NN 50000
#define NE 1600000
#define FIN 512
#define FHID 128
#define FOUT 64

// ---- scratch (static device globals; no allocations anywhere) ----
__device__ int   g_is64;
__device__ float g_dinv[NN];
__device__ int   g_count[NN];
__device__ int   g_ptr[NN + 1];
__device__ int   g_cursor[NN];
__device__ int   g_srcs[NE];
__device__ float g_w[NE];
__device__ float g_tmp1[(size_t)NN * FHID];  // x@W1 (pre-propagation)
__device__ float g_h1[(size_t)NN * FHID];    // layer-1 output
__device__ float g_tmp2[(size_t)NN * FOUT];  // h1@W2
__device__ float g_h2[(size_t)NN * FOUT];    // layer-2 output

// Edge index may be int64 (as authored) or int32 (JAX default canonicalizes).
__device__ __forceinline__ int edge_at(const void* p, long long idx) {
    return g_is64 ? (int)((const long long*)p)[idx] : ((const int*)p)[idx];
}

// Detect dtype: if int64 little-endian with values in [0, 50000), every odd
// 32-bit word (high half) is 0. For int32 data, odd words are uniform values
// in [0,50000) -> P(all 128 sampled are zero) ~ 0.
__global__ void detect_kernel(const unsigned int* __restrict__ p) {
    if (threadIdx.x == 0 && blockIdx.x == 0) {
        int all0 = 1;
        for (int i = 1; i < 256 && all0; i += 2)
            if (p[i] != 0u) all0 = 0;
        g_is64 = all0;
    }
}

__global__ void zero_kernel() {
    int i = blockIdx.x * blockDim.x + threadIdx.x;
    if (i < NN) g_count[i] = 0;
}

__global__ void degree_kernel(const void* __restrict__ ei, int E) {
    int i = blockIdx.x * blockDim.x + threadIdx.x;
    if (i < E) {
        int d = edge_at(ei, (long long)E + i);
        atomicAdd(&g_count[d], 1);
    }
}

__global__ void dinv_kernel() {
    int i = blockIdx.x * blockDim.x + threadIdx.x;
    if (i < NN) g_dinv[i] = rsqrtf((float)(g_count[i] + 1));  // +1 self loop
}

// Exclusive prefix sum over g_count -> g_ptr, g_cursor. Single block, 1024 thr.
__global__ void scan_kernel() {
    __shared__ int warpsums[32];
    __shared__ int s_carry;
    int tid = threadIdx.x, lane = tid & 31, wid = tid >> 5;
    if (tid == 0) s_carry = 0;
    __syncthreads();
    for (int base = 0; base < NN; base += 1024) {
        int i = base + tid;
        int v = (i < NN) ? g_count[i] : 0;
        int x = v;
#pragma unroll
        for (int off = 1; off < 32; off <<= 1) {
            int y = __shfl_up_sync(0xffffffffu, x, off);
            if (lane >= off) x += y;
        }
        if (lane == 31) warpsums[wid] = x;
        __syncthreads();
        if (wid == 0) {
            int s = warpsums[lane];
#pragma unroll
            for (int off = 1; off < 32; off <<= 1) {
                int y = __shfl_up_sync(0xffffffffu, s, off);
                if (lane >= off) s += y;
            }
            warpsums[lane] = s;
        }
        __syncthreads();
        int woff = wid ? warpsums[wid - 1] : 0;
        int incl = x + woff + s_carry;
        if (i < NN) { g_ptr[i] = incl - v; g_cursor[i] = incl - v; }
        __syncthreads();
        if (tid == 1023) s_carry = incl;
        __syncthreads();
    }
    if (tid == 0) g_ptr[NN] = s_carry;
}

__global__ void build_kernel(const void* __restrict__ ei, int E) {
    int i = blockIdx.x * blockDim.x + threadIdx.x;
    if (i < E) {
        int s = edge_at(ei, i);
        int d = edge_at(ei, (long long)E + i);
        int pos = atomicAdd(&g_cursor[d], 1);
        g_srcs[pos] = s;
        g_w[pos] = g_dinv[s] * g_dinv[d];
    }
}

// ---- SIMT fp32 GEMM: C[M,N] = A[M,K] @ B[K,N], row-major, N,K compile-time.
// GEMM_ID==1: A = external (x), C = g_tmp1.  GEMM_ID==2: A = g_h1, C = g_tmp2.
template <int BM, int BN, int BK, int TM, int TN, int N, int K, int GEMM_ID>
__global__ void sgemm_kernel(const float* __restrict__ Aext,
                             const float* __restrict__ B, int M) {
    constexpr int THREADS = (BM / TM) * (BN / TN);  // 256
    __shared__ float As[BK][BM + 1];
    __shared__ float Bs[BK][BN];
    const float* A = (GEMM_ID == 1) ? Aext : (const float*)g_h1;
    float* C = (GEMM_ID == 1) ? (float*)g_tmp1 : (float*)g_tmp2;

    int tid = threadIdx.x;
    int tx = tid % (BN / TN);
    int ty = tid / (BN / TN);
    int m0 = blockIdx.x * BM;
    float acc[TM][TN] = {};

    constexpr int A_F4 = BM * BK / 4;
    constexpr int B_F4 = BK * BN / 4;

    for (int k0 = 0; k0 < K; k0 += BK) {
#pragma unroll
        for (int i = tid; i < A_F4; i += THREADS) {
            int r = i / (BK / 4);
            int c4 = i % (BK / 4);
            int gr = m0 + r;
            float4 v = make_float4(0.f, 0.f, 0.f, 0.f);
            if (gr < M)
                v = *(const float4*)(A + (size_t)gr * K + k0 + c4 * 4);
            As[c4 * 4 + 0][r] = v.x;
            As[c4 * 4 + 1][r] = v.y;
            As[c4 * 4 + 2][r] = v.z;
            As[c4 * 4 + 3][r] = v.w;
        }
#pragma unroll
        for (int i = tid; i < B_F4; i += THREADS) {
            int r = i / (BN / 4);
            int c4 = i % (BN / 4);
            *(float4*)&Bs[r][c4 * 4] =
                *(const float4*)(B + (size_t)(k0 + r) * N + c4 * 4);
        }
        __syncthreads();
#pragma unroll
        for (int k = 0; k < BK; k++) {
            float ra[TM], rb[TN];
#pragma unroll
            for (int i = 0; i < TM; i++) ra[i] = As[k][ty * TM + i];
#pragma unroll
            for (int j = 0; j < TN; j++) rb[j] = Bs[k][tx * TN + j];
#pragma unroll
            for (int i = 0; i < TM; i++)
#pragma unroll
                for (int j = 0; j < TN; j++) acc[i][j] += ra[i] * rb[j];
        }
        __syncthreads();
    }
#pragma unroll
    for (int i = 0; i < TM; i++) {
        int gr = m0 + ty * TM + i;
        if (gr < M) {
#pragma unroll
            for (int j = 0; j < TN; j++)
                C[(size_t)gr * N + tx * TN + j] = acc[i][j];
        }
    }
}

// ---- Pull-based propagation: out[i] = sum_e w[e]*hin[src[e]] + dinv^2*hin[i] + b
// One node per CTA of F threads; edge data staged through shared memory.
template <int F, bool RELU, bool LAYER1>
__global__ void prop_kernel(const float* __restrict__ bias) {
    __shared__ int ss[128];
    __shared__ float sw[128];
    const float* hin = LAYER1 ? (const float*)g_tmp1 : (const float*)g_tmp2;
    float* hout = LAYER1 ? (float*)g_h1 : (float*)g_h2;

    int node = blockIdx.x;
    int f = threadIdx.x;
    float di = g_dinv[node];
    float a0 = di * di * hin[(size_t)node * F + f];  // self loop
    float a1 = 0.f, a2 = 0.f, a3 = 0.f;

    int beg = g_ptr[node], end = g_ptr[node + 1];
    for (int c = beg; c < end; c += 128) {
        int n = min(128, end - c);
        for (int i = f; i < n; i += F) {
            ss[i] = g_srcs[c + i];
            sw[i] = g_w[c + i];
        }
        __syncthreads();
        int i = 0;
        for (; i + 4 <= n; i += 4) {
            int s0 = ss[i], s1 = ss[i + 1], s2 = ss[i + 2], s3 = ss[i + 3];
            float w0 = sw[i], w1 = sw[i + 1], w2 = sw[i + 2], w3 = sw[i + 3];
            a0 += w0 * hin[(size_t)s0 * F + f];
            a1 += w1 * hin[(size_t)s1 * F + f];
            a2 += w2 * hin[(size_t)s2 * F + f];
            a3 += w3 * hin[(size_t)s3 * F + f];
        }
        for (; i < n; i++) a0 += sw[i] * hin[(size_t)ss[i] * F + f];
        __syncthreads();
    }
    float acc = (a0 + a1) + (a2 + a3) + bias[f];
    if (RELU) acc = fmaxf(acc, 0.f);
    hout[(size_t)node * F + f] = acc;
}

// ---- Fused final linear (h2 @ Wl + bl) + log_softmax over 64 classes.
// 8 warps per block, one row per warp. Wl cached in shared.
__global__ void final_kernel(const float* __restrict__ Wl,
                             const float* __restrict__ bl,
                             float* __restrict__ out, int M) {
    __shared__ float sW[64 * 64];
    __shared__ float sb[64];
    int tid = threadIdx.x;
    for (int i = tid; i < 64 * 64; i += 256) sW[i] = Wl[i];
    if (tid < 64) sb[tid] = bl[tid];
    __syncthreads();

    int lane = tid & 31, warp = tid >> 5;
    int r = blockIdx.x * 8 + warp;
    if (r >= M) return;

    const float* hrow = (const float*)g_h2 + (size_t)r * 64;
    float x0 = hrow[lane], x1 = hrow[lane + 32];
    float acc0 = 0.f, acc1 = 0.f;
#pragma unroll
    for (int k = 0; k < 64; k++) {
        float xk = __shfl_sync(0xffffffffu, (k < 32) ? x0 : x1, k & 31);
        acc0 += xk * sW[k * 64 + lane];
        acc1 += xk * sW[k * 64 + lane + 32];
    }
    acc0 += sb[lane];
    acc1 += sb[lane + 32];

    float m = fmaxf(acc0, acc1);
#pragma unroll
    for (int off = 16; off; off >>= 1)
        m = fmaxf(m, __shfl_xor_sync(0xffffffffu, m, off));
    float s = expf(acc0 - m) + expf(acc1 - m);
#pragma unroll
    for (int off = 16; off; off >>= 1)
        s += __shfl_xor_sync(0xffffffffu, s, off);
    float lse = m + logf(s);

    out[(size_t)r * 64 + lane] = acc0 - lse;
    out[(size_t)r * 64 + lane + 32] = acc1 - lse;
}

// ---------------------------------------------------------------------------
extern "C" void kernel_launch(void* const* d_in, const int* in_sizes, int n_in,
                              void* d_out, int out_size) {
    const float* x  = (const float*)d_in[0];
    const void*  ei = d_in[1];
    const float* W1 = (const float*)d_in[2];
    const float* b1 = (const float*)d_in[3];
    const float* W2 = (const float*)d_in[4];
    const float* b2 = (const float*)d_in[5];
    const float* Wl = (const float*)d_in[6];
    const float* bl = (const float*)d_in[7];
    float* out = (float*)d_out;

    int M = in_sizes[0] / FIN;       // 50000
    int E = in_sizes[1] / 2;         // 1600000 (element count same for i32/i64)

    detect_kernel<<<1, 32>>>((const unsigned int*)ei);
    zero_kernel<<<(NN + 255) / 256, 256>>>();
    degree_kernel<<<(E + 255) / 256, 256>>>(ei, E);
    dinv_kernel<<<(NN + 255) / 256, 256>>>();
    scan_kernel<<<1, 1024>>>();
    build_kernel<<<(E + 255) / 256, 256>>>(ei, E);

    int gblocks = (M + 127) / 128;
    sgemm_kernel<128, 128, 16, 8, 8, FHID, FIN, 1><<<gblocks, 256>>>(x, W1, M);
    prop_kernel<FHID, true, true><<<M, FHID>>>(b1);
    sgemm_kernel<128, 64, 16, 8, 4, FOUT, FHID, 2><<<gblocks, 256>>>(nullptr, W2, M);
    prop_kernel<FOUT, false, false><<<M, FOUT>>>(b2);
    final_kernel<<<(M + 7) / 8, 256>>>(Wl, bl, out, M);
}